// round 4
// baseline (speedup 1.0000x reference)
#include <cuda_runtime.h>

// HilbertSimulator: 4-qubit statevector sim, BATCH=2^21, DIM=16.
// out[b,j] = <Z_j> after RY-encoding(x), RY(weights), CNOT ring.
// Memory-bound: 16B in + 16B out per element.

#define BATCH_N 2097152
#define TPB 256

__global__ void __launch_bounds__(TPB)
hilbert_kernel(const float4* __restrict__ x,
               const float*  __restrict__ w,
               float4*       __restrict__ out)
{
    const int b = blockIdx.x * TPB + threadIdx.x;

    const float4 xv = x[b];

    // sincos of data angles. qubit i acts on bit (3-i).
    float c0, s0, c1, s1, c2, s2, c3, s3;
    __sincosf(xv.x, &s0, &c0);
    __sincosf(xv.y, &s1, &c1);
    __sincosf(xv.z, &s2, &c2);
    __sincosf(xv.w, &s3, &c3);

    // Product state: st[k] = f0(bit3) f1(bit2) f2(bit1) f3(bit0),
    // f_i(0)=cos(x_i), f_i(1)=sin(x_i)
    float t01[4], t23[4];
    t01[0] = c0 * c1; t01[1] = c0 * s1; t01[2] = s0 * c1; t01[3] = s0 * s1;
    t23[0] = c2 * c3; t23[1] = c2 * s3; t23[2] = s2 * c3; t23[3] = s2 * s3;

    float st[16];
#pragma unroll
    for (int k = 0; k < 16; k++)
        st[k] = t01[k >> 2] * t23[k & 3];

    // Weight rotations (same angle across batch; L2-broadcast load).
    float wc[4], ws[4];
#pragma unroll
    for (int i = 0; i < 4; i++)
        __sincosf(__ldg(w + i), &ws[i], &wc[i]);

    // RY(weights[q]) on qubit q  (bit mask m = 8 >> q)
#pragma unroll
    for (int q = 0; q < 4; q++) {
        const int m = 8 >> q;
#pragma unroll
        for (int k = 0; k < 16; k++) {
            if (k & m) continue;
            const float a  = st[k];
            const float bb = st[k | m];
            st[k]     = wc[q] * a - ws[q] * bb;
            st[k | m] = ws[q] * a + wc[q] * bb;
        }
    }

    // CNOT ring as gathers: new[k] = st[(k & cbit) ? k ^ tbit : k]
    // pairs (control,target) bit-values: (8,4),(4,2),(2,1),(1,8)
    const int cb[4] = {8, 4, 2, 1};
    const int tb[4] = {4, 2, 1, 8};
#pragma unroll
    for (int pi = 0; pi < 4; pi++) {
        float ns[16];
#pragma unroll
        for (int k = 0; k < 16; k++) {
            const int src = (k & cb[pi]) ? (k ^ tb[pi]) : k;
            ns[k] = st[src];
        }
#pragma unroll
        for (int k = 0; k < 16; k++) st[k] = ns[k];
    }

    // probs and Z expectations: out_j = sum_k (+/-) st[k]^2,
    // sign negative when bit (3-j) of k is set.
    float p[16];
#pragma unroll
    for (int k = 0; k < 16; k++) p[k] = st[k] * st[k];

    float o0 = 0.f, o1 = 0.f, o2 = 0.f, o3 = 0.f;
#pragma unroll
    for (int k = 0; k < 16; k++) {
        o0 += (k & 8) ? -p[k] : p[k];
        o1 += (k & 4) ? -p[k] : p[k];
        o2 += (k & 2) ? -p[k] : p[k];
        o3 += (k & 1) ? -p[k] : p[k];
    }

    out[b] = make_float4(o0, o1, o2, o3);
}

extern "C" void kernel_launch(void* const* d_in, const int* in_sizes, int n_in,
                              void* d_out, int out_size)
{
    const float4* x = (const float4*)d_in[0];   // (BATCH, 4) float32
    const float*  w = (const float*)d_in[1];    // (1, 4) float32
    float4* out = (float4*)d_out;               // (BATCH, 4) float32

    const int n = in_sizes[0] / 4;              // BATCH
    hilbert_kernel<<<n / TPB, TPB>>>(x, w, out);
}

// round 5
// speedup vs baseline: 1.9942x; 1.9942x over previous
#include <cuda_runtime.h>

// HilbertSimulator: 4-qubit statevector sim, BATCH=2^21.
// Closed form (derived exactly from the reference circuit):
//   Ci   = cos(2*(x_i + w_i))      (weight RY fuses into the encoding angle;
//                                   CNOT-ring perm + Z-measure collapse to
//                                   rank-1 sign patterns over the product state)
//   out  = ( C1*C2*C3, C0*C1, C0*C1*C2, C0*C1*C2*C3 )
// Pure streaming: 16B in + 16B out per element.

#define TPB 256
#define EPT 2   // elements per thread (MLP)

__global__ void __launch_bounds__(TPB)
hilbert_kernel(const float4* __restrict__ x,
               const float*  __restrict__ w,
               float4*       __restrict__ out)
{
    // uniform weights (L2-broadcast)
    const float w0 = __ldg(w + 0);
    const float w1 = __ldg(w + 1);
    const float w2 = __ldg(w + 2);
    const float w3 = __ldg(w + 3);

    const int base = blockIdx.x * (TPB * EPT) + threadIdx.x;

    float4 xv[EPT];
#pragma unroll
    for (int e = 0; e < EPT; e++)
        xv[e] = x[base + e * TPB];           // coalesced 128B/warp per load

#pragma unroll
    for (int e = 0; e < EPT; e++) {
        const float C0 = __cosf(2.0f * (xv[e].x + w0));
        const float C1 = __cosf(2.0f * (xv[e].y + w1));
        const float C2 = __cosf(2.0f * (xv[e].z + w2));
        const float C3 = __cosf(2.0f * (xv[e].w + w3));

        const float t01 = C0 * C1;
        const float c23 = C2 * C3;

        out[base + e * TPB] = make_float4(C1 * c23,       // <Z0>
                                          t01,            // <Z1>
                                          t01 * C2,       // <Z2>
                                          t01 * c23);     // <Z3>
    }
}

extern "C" void kernel_launch(void* const* d_in, const int* in_sizes, int n_in,
                              void* d_out, int out_size)
{
    const float4* x = (const float4*)d_in[0];   // (BATCH, 4) float32
    const float*  w = (const float*)d_in[1];    // (1, 4) float32
    float4* out = (float4*)d_out;               // (BATCH, 4) float32

    const int n = in_sizes[0] / 4;              // BATCH = 2^21
    hilbert_kernel<<<n / (TPB * EPT), TPB>>>(x, w, out);
}

// round 8
// speedup vs baseline: 2.0358x; 1.0209x over previous
#include <cuda_runtime.h>

// HilbertSimulator: 4-qubit statevector sim, BATCH=2^21.
// Closed form (exact):
//   Ci  = cos(2*(x_i + w_i))
//   out = ( C1*C2*C3, C0*C1, C0*C1*C2, C0*C1*C2*C3 )
// Pure streaming: 16B in + 16B out per element. EPT=4 for MLP.

#define TPB 256
#define EPT 4   // elements per thread (front-batched LDG.128s)

__global__ void __launch_bounds__(TPB)
hilbert_kernel(const float4* __restrict__ x,
               const float*  __restrict__ w,
               float4*       __restrict__ out)
{
    // uniform weights (L2-broadcast)
    const float w0 = __ldg(w + 0);
    const float w1 = __ldg(w + 1);
    const float w2 = __ldg(w + 2);
    const float w3 = __ldg(w + 3);

    const int base = blockIdx.x * (TPB * EPT) + threadIdx.x;

    // Front-batch all loads: 4 independent LDG.128 per thread (MLP_p1=4),
    // each warp-coalesced to 4x128B lines.
    float4 xv[EPT];
#pragma unroll
    for (int e = 0; e < EPT; e++)
        xv[e] = x[base + e * TPB];

    float4 ov[EPT];
#pragma unroll
    for (int e = 0; e < EPT; e++) {
        const float C0 = __cosf(2.0f * (xv[e].x + w0));
        const float C1 = __cosf(2.0f * (xv[e].y + w1));
        const float C2 = __cosf(2.0f * (xv[e].z + w2));
        const float C3 = __cosf(2.0f * (xv[e].w + w3));

        const float t01 = C0 * C1;
        const float c23 = C2 * C3;

        ov[e] = make_float4(C1 * c23,     // <Z0>
                            t01,          // <Z1>
                            t01 * C2,     // <Z2>
                            t01 * c23);   // <Z3>
    }

#pragma unroll
    for (int e = 0; e < EPT; e++)
        out[base + e * TPB] = ov[e];
}

extern "C" void kernel_launch(void* const* d_in, const int* in_sizes, int n_in,
                              void* d_out, int out_size)
{
    const float4* x = (const float4*)d_in[0];   // (BATCH, 4) float32
    const float*  w = (const float*)d_in[1];    // (1, 4) float32
    float4* out = (float4*)d_out;               // (BATCH, 4) float32

    const int n = in_sizes[0] / 4;              // BATCH = 2^21
    hilbert_kernel<<<n / (TPB * EPT), TPB>>>(x, w, out);
}